// round 2
// baseline (speedup 1.0000x reference)
#include <cuda_runtime.h>

// IWTBlock: 1x1 conv (per-pixel GEMM 256->256) + inverse Haar (4ch -> 2x2 spatial).
//
// Per batch b: Y_b = W(256x256) @ X_b(256x16384) + bias, then
//   out[b][g][2h+i][2w+j] = 0.5*(y[4g]+s_i*y[4g+1]+s_j*y[4g+2]+s_i*s_j*y[4g+3])
// with s_0=+1, s_1=-1 (2D Haar butterfly; conv_transpose stride2/k2 has no overlap).
//
// Kernel: 128(M) x 128(N) x 8(K) double-buffered fp32 tile GEMM.
// Block = one h-row of 128 pixels x 128 output channels. 256 threads, 8x8
// micro-tile per thread. Steady-state mainloop has no tail predicate (last
// K-step peeled). Epilogue (bias + Haar + float4 stores) is thread-local.

static constexpr int C_IN = 256;   // input channels == K
static constexpr int HH   = 128;
static constexpr int WW   = 128;
static constexpr int PIX  = HH * WW;        // 16384
static constexpr int OUTG = 4 * PIX;        // per-(b,g) output elements: 256*256

__global__ __launch_bounds__(256, 2)
void iwt_gemm_kernel(const float* __restrict__ x,
                     const float* __restrict__ wmat,
                     const float* __restrict__ bias,
                     float* __restrict__ out)
{
    const int b  = blockIdx.z;          // batch
    const int m0 = blockIdx.y * 128;    // output-channel tile base (0 or 128)
    const int h  = blockIdx.x;          // spatial row (pixels p = h*128 + w)

    // x[b][c][h][w] : b*C*PIX + c*PIX + h*WW + w
    const float* Xb = x + ((size_t)b * C_IN) * PIX + (size_t)h * WW;

    __shared__ float As[2][8][128];   // As[buf][k][o]  (transposed W tile)
    __shared__ float Bs[2][8][128];   // Bs[buf][k][w]

    const int tid = threadIdx.x;
    const int ty  = tid >> 4;         // 0..15  -> channel micro-row
    const int tx  = tid & 15;         // 0..15  -> pixel micro-col

    // A load: thread -> float4 of W[(m0+ar), ac..ac+3 (+k0)]
    const int ar = tid >> 1;          // 0..127
    const int ac = (tid & 1) << 2;    // 0 or 4
    // B load: thread -> float4 of X[(k0+br), bc..bc+3]
    const int br = tid >> 5;          // 0..7
    const int bc = (tid & 31) << 2;   // 0..124

    const float* aptr = wmat + (size_t)(m0 + ar) * C_IN + ac;
    const float* bptr = Xb + (size_t)br * PIX + bc;

    float acc[8][8];
    #pragma unroll
    for (int i = 0; i < 8; i++)
        #pragma unroll
        for (int j = 0; j < 8; j++) acc[i][j] = 0.f;

    // prologue: stage k0 = 0
    {
        float4 va = *reinterpret_cast<const float4*>(aptr);
        As[0][ac + 0][ar] = va.x;
        As[0][ac + 1][ar] = va.y;
        As[0][ac + 2][ar] = va.z;
        As[0][ac + 3][ar] = va.w;
        float4 vb = *reinterpret_cast<const float4*>(bptr);
        *reinterpret_cast<float4*>(&Bs[0][br][bc]) = vb;
    }
    __syncthreads();

    int buf = 0;
    // steady state: 31 iterations, always prefetch next stage (no predicate)
    for (int k0 = 0; k0 < C_IN - 8; k0 += 8) {
        float4 va = *reinterpret_cast<const float4*>(aptr + (k0 + 8));
        float4 vb = *reinterpret_cast<const float4*>(bptr + (size_t)(k0 + 8) * PIX);
        As[buf ^ 1][ac + 0][ar] = va.x;
        As[buf ^ 1][ac + 1][ar] = va.y;
        As[buf ^ 1][ac + 2][ar] = va.z;
        As[buf ^ 1][ac + 3][ar] = va.w;
        *reinterpret_cast<float4*>(&Bs[buf ^ 1][br][bc]) = vb;

        #pragma unroll
        for (int kk = 0; kk < 8; kk++) {
            float a[8], bv[8];
            *reinterpret_cast<float4*>(&a[0])  = *reinterpret_cast<const float4*>(&As[buf][kk][ty * 8]);
            *reinterpret_cast<float4*>(&a[4])  = *reinterpret_cast<const float4*>(&As[buf][kk][ty * 8 + 4]);
            *reinterpret_cast<float4*>(&bv[0]) = *reinterpret_cast<const float4*>(&Bs[buf][kk][tx * 8]);
            *reinterpret_cast<float4*>(&bv[4]) = *reinterpret_cast<const float4*>(&Bs[buf][kk][tx * 8 + 4]);
            #pragma unroll
            for (int i = 0; i < 8; i++)
                #pragma unroll
                for (int j = 0; j < 8; j++)
                    acc[i][j] += a[i] * bv[j];
        }
        __syncthreads();
        buf ^= 1;
    }
    // peeled last K-step (no prefetch)
    #pragma unroll
    for (int kk = 0; kk < 8; kk++) {
        float a[8], bv[8];
        *reinterpret_cast<float4*>(&a[0])  = *reinterpret_cast<const float4*>(&As[buf][kk][ty * 8]);
        *reinterpret_cast<float4*>(&a[4])  = *reinterpret_cast<const float4*>(&As[buf][kk][ty * 8 + 4]);
        *reinterpret_cast<float4*>(&bv[0]) = *reinterpret_cast<const float4*>(&Bs[buf][kk][tx * 8]);
        *reinterpret_cast<float4*>(&bv[4]) = *reinterpret_cast<const float4*>(&Bs[buf][kk][tx * 8 + 4]);
        #pragma unroll
        for (int i = 0; i < 8; i++)
            #pragma unroll
            for (int j = 0; j < 8; j++)
                acc[i][j] += a[i] * bv[j];
    }

    // ---- epilogue: bias + inverse Haar butterfly + coalesced stores ----
    float bvv[8];
    #pragma unroll
    for (int i = 0; i < 8; i++) bvv[i] = __ldg(bias + m0 + ty * 8 + i);

    float* outb = out + (size_t)b * 64 * OUTG;

    #pragma unroll
    for (int half = 0; half < 2; half++) {
        const int i0 = half * 4;
        const int g  = (m0 + ty * 8 + i0) >> 2;   // Haar group index (0..63)
        float row0[16], row1[16];
        #pragma unroll
        for (int j = 0; j < 8; j++) {
            float y0 = acc[i0 + 0][j] + bvv[i0 + 0];
            float y1 = acc[i0 + 1][j] + bvv[i0 + 1];
            float y2 = acc[i0 + 2][j] + bvv[i0 + 2];
            float y3 = acc[i0 + 3][j] + bvv[i0 + 3];
            float p = y0 + y1, q = y2 + y3;
            float r = y0 - y1, t = y2 - y3;
            row0[2 * j + 0] = 0.5f * (p + q);   // (i=0, j=0)
            row0[2 * j + 1] = 0.5f * (p - q);   // (i=0, j=1)
            row1[2 * j + 0] = 0.5f * (r + t);   // (i=1, j=0)
            row1[2 * j + 1] = 0.5f * (r - t);   // (i=1, j=1)
        }
        // out[b][g][2h + i][2w + j]; this thread covers cols 16*tx .. 16*tx+15
        float* o0 = outb + (size_t)g * OUTG + (size_t)(2 * h) * 256 + 16 * tx;
        float* o1 = o0 + 256;
        #pragma unroll
        for (int v = 0; v < 4; v++) {
            *reinterpret_cast<float4*>(o0 + 4 * v) =
                make_float4(row0[4 * v], row0[4 * v + 1], row0[4 * v + 2], row0[4 * v + 3]);
            *reinterpret_cast<float4*>(o1 + 4 * v) =
                make_float4(row1[4 * v], row1[4 * v + 1], row1[4 * v + 2], row1[4 * v + 3]);
        }
    }
}

extern "C" void kernel_launch(void* const* d_in, const int* in_sizes, int n_in,
                              void* d_out, int out_size)
{
    const float* x    = (const float*)d_in[0];   // [16,256,128,128]
    const float* w    = (const float*)d_in[1];   // [256,256]
    const float* bias = (const float*)d_in[2];   // [256]
    float* out        = (float*)d_out;           // [16,64,256,256]

    dim3 grid(HH, 2, 16);   // h-rows x M-tiles x batches = 4096 blocks
    iwt_gemm_kernel<<<grid, 256>>>(x, w, bias, out);
}

// round 7
// speedup vs baseline: 2.2216x; 2.2216x over previous
#include <cuda_runtime.h>
#include <cuda_bf16.h>
#include <cstdint>

// IWTBlock via mma.sync bf16 3-split GEMM (Wh*Xh + Wh*Xl + Wl*Xh), fp32 acc.
// Static smem only (32KB) -- no dynamic-smem opt-in, no cudaFuncSetAttribute.
// Per batch: Y = W(256x256) @ X(256x16384) + bias; inverse-Haar epilogue.
// CTA: M=128 oc x N=128 pixels (one h-row), K=256 in 8 chunks of 32.
// 8 warps: wm=wid&3 (32 oc rows), wn=wid>>2 (64 pixel cols). Warp tile 32x64.

static constexpr int C_IN = 256;
static constexpr int HH = 128, WW = 128;
static constexpr int PIX = HH * WW;
static constexpr int OUTG = 4 * PIX;
static constexpr int KCH = 32;
static constexpr int NCHUNKS = C_IN / KCH;     // 8

// SMEM (bytes): A tiles [128 m][32 k] bf16 = 64B rows (8KB each);
//               B tiles [32 k][128 n] bf16 = 256B rows (8KB each). Total 32KB.
static constexpr int SM_AHI = 0;
static constexpr int SM_ALO = 8192;
static constexpr int SM_BHI = 16384;
static constexpr int SM_BLO = 24576;
static constexpr int SMEM_BYTES = 32768;
// Post-mainloop: Ds32 = 32 ch x 132 floats (16896B), overlaps tile region.
static constexpr int DS_STRIDE = 132;          // floats; 132*4 % 16 == 0 (float4 ok)

__device__ __forceinline__ uint32_t smem_u32(const void* p) {
    uint32_t a;
    asm("{ .reg .u64 t; cvta.to.shared.u64 t, %1; cvt.u32.u64 %0, t; }" : "=r"(a) : "l"(p));
    return a;
}
// A swizzle (64B rows, SW64): XOR bits[4:5] with bits[7:8]
__device__ __forceinline__ uint32_t swA(uint32_t o) { return o ^ ((o >> 3) & 0x30); }
// B swizzle (256B rows): XOR bits[4:6] with bits[8:10]
__device__ __forceinline__ uint32_t swB(uint32_t o) { return o ^ ((o >> 4) & 0x70); }

__device__ __forceinline__ void ldsm_x4(uint32_t (&r)[4], uint32_t addr) {
    asm volatile("ldmatrix.sync.aligned.m8n8.x4.shared.b16 {%0,%1,%2,%3}, [%4];"
                 : "=r"(r[0]), "=r"(r[1]), "=r"(r[2]), "=r"(r[3]) : "r"(addr));
}
__device__ __forceinline__ void ldsm_x4_t(uint32_t (&r)[4], uint32_t addr) {
    asm volatile("ldmatrix.sync.aligned.m8n8.x4.trans.shared.b16 {%0,%1,%2,%3}, [%4];"
                 : "=r"(r[0]), "=r"(r[1]), "=r"(r[2]), "=r"(r[3]) : "r"(addr));
}
__device__ __forceinline__ void mma_bf16(float (&d)[4], const uint32_t (&a)[4],
                                         uint32_t b0, uint32_t b1) {
    asm volatile("mma.sync.aligned.m16n8k16.row.col.f32.bf16.bf16.f32 "
                 "{%0,%1,%2,%3}, {%4,%5,%6,%7}, {%8,%9}, {%0,%1,%2,%3};"
                 : "+f"(d[0]), "+f"(d[1]), "+f"(d[2]), "+f"(d[3])
                 : "r"(a[0]), "r"(a[1]), "r"(a[2]), "r"(a[3]), "r"(b0), "r"(b1));
}

__device__ __forceinline__ uint32_t pack_hi(float a, float b, float& ra, float& rb) {
    __nv_bfloat16 ha = __float2bfloat16_rn(a), hb = __float2bfloat16_rn(b);
    ra = a - __bfloat162float(ha);
    rb = b - __bfloat162float(hb);
    return (uint32_t)__bfloat16_as_ushort(ha) | ((uint32_t)__bfloat16_as_ushort(hb) << 16);
}
__device__ __forceinline__ uint32_t pack_lo(float a, float b) {
    return (uint32_t)__bfloat16_as_ushort(__float2bfloat16_rn(a)) |
           ((uint32_t)__bfloat16_as_ushort(__float2bfloat16_rn(b)) << 16);
}

__global__ __launch_bounds__(256, 2)
void iwt_hmma_kernel(const float* __restrict__ x,
                     const float* __restrict__ wmat,
                     const float* __restrict__ bias,
                     float* __restrict__ out)
{
    __shared__ __align__(1024) char smem[SMEM_BYTES];
    const uint32_t sb = smem_u32(smem);
    const int tid = threadIdx.x, wid = tid >> 5, lane = tid & 31;
    const int b = blockIdx.z, m0 = blockIdx.y * 128, h = blockIdx.x;
    const float* Xb = x + ((size_t)b * C_IN) * PIX + (size_t)h * WW;

    const int wm = wid & 3;          // m-block: rows wm*32 .. +31
    const int wn = wid >> 2;         // n-block: cols wn*64 .. +63

    // W conversion: tid&7 -> k4 (float4 over 32 k), tid>>3 -> row (+32*it)
    const int wk4   = (tid & 7) * 4;
    const int wrow0 = tid >> 3;      // 0..31
    // X conversion: tid&15 -> n8 (8 consecutive pixels), tid>>4 -> k (+16*it)
    const int xn8 = (tid & 15) * 8;
    const int xk0 = tid >> 4;        // 0..15

    // ldmatrix lane address components
    const int li  = lane & 7;        // row within 8x8 matrix
    const int seg = lane >> 3;       // which 8x8 matrix
    const int a_row_off = li + (seg & 1) * 8;
    const int a_col_off = (seg >> 1) * 8;
    const int b_k_off = li + (seg & 1) * 8;
    const int b_n_off = (seg >> 1) * 8;

    float acc[2][8][4];
    #pragma unroll
    for (int i = 0; i < 2; i++)
        #pragma unroll
        for (int j = 0; j < 8; j++)
            #pragma unroll
            for (int v = 0; v < 4; v++) acc[i][j][v] = 0.f;

    for (int c = 0; c < NCHUNKS; c++) {
        if (c > 0) __syncthreads();          // all warps done reading chunk c-1
        const int kb = c * KCH;

        // ---- W chunk -> A_hi/A_lo : [m][k] bf16, 64B rows, swA ----
        #pragma unroll
        for (int it = 0; it < 4; it++) {
            const int row = wrow0 + 32 * it;
            float4 v = *reinterpret_cast<const float4*>(
                wmat + (size_t)(m0 + row) * C_IN + kb + wk4);
            float r0, r1, r2, r3;
            uint32_t h01 = pack_hi(v.x, v.y, r0, r1);
            uint32_t h23 = pack_hi(v.z, v.w, r2, r3);
            uint32_t off = swA((uint32_t)(row * 64 + wk4 * 2));
            *reinterpret_cast<uint2*>(smem + SM_AHI + off) = make_uint2(h01, h23);
            *reinterpret_cast<uint2*>(smem + SM_ALO + off) =
                make_uint2(pack_lo(r0, r1), pack_lo(r2, r3));
        }

        // ---- X chunk -> B_hi/B_lo : [k][n] bf16, 256B rows, swB ----
        #pragma unroll
        for (int it = 0; it < 2; it++) {
            const int k = xk0 + 16 * it;
            const float* src = Xb + (size_t)(kb + k) * PIX + xn8;
            float4 v0 = *reinterpret_cast<const float4*>(src);
            float4 v1 = *reinterpret_cast<const float4*>(src + 4);
            float r[8];
            uint32_t h0 = pack_hi(v0.x, v0.y, r[0], r[1]);
            uint32_t h1 = pack_hi(v0.z, v0.w, r[2], r[3]);
            uint32_t h2 = pack_hi(v1.x, v1.y, r[4], r[5]);
            uint32_t h3 = pack_hi(v1.z, v1.w, r[6], r[7]);
            uint32_t off = swB((uint32_t)(k * 256 + xn8 * 2));
            *reinterpret_cast<uint4*>(smem + SM_BHI + off) = make_uint4(h0, h1, h2, h3);
            *reinterpret_cast<uint4*>(smem + SM_BLO + off) =
                make_uint4(pack_lo(r[0], r[1]), pack_lo(r[2], r[3]),
                           pack_lo(r[4], r[5]), pack_lo(r[6], r[7]));
        }

        __syncthreads();

        // ---- mainloop: 2 k16 steps, 48 HMMA each ----
        #pragma unroll
        for (int s = 0; s < 2; s++) {
            const int k0 = s * 16;
            uint32_t ah[2][4], al[2][4];
            #pragma unroll
            for (int mt = 0; mt < 2; mt++) {
                const int R = wm * 32 + mt * 16 + a_row_off;
                const uint32_t aoff = swA((uint32_t)(R * 64 + (k0 + a_col_off) * 2));
                ldsm_x4(ah[mt], sb + SM_AHI + aoff);
                ldsm_x4(al[mt], sb + SM_ALO + aoff);
            }
            #pragma unroll
            for (int nt = 0; nt < 4; nt++) {
                const int n0 = wn * 64 + nt * 16;
                const uint32_t boff = swB((uint32_t)((k0 + b_k_off) * 256 +
                                                     (n0 + b_n_off) * 2));
                uint32_t bh[4], bl[4];
                ldsm_x4_t(bh, sb + SM_BHI + boff);
                ldsm_x4_t(bl, sb + SM_BLO + boff);
                #pragma unroll
                for (int t2 = 0; t2 < 2; t2++) {
                    const int nidx = nt * 2 + t2;
                    #pragma unroll
                    for (int mt = 0; mt < 2; mt++) {
                        mma_bf16(acc[mt][nidx], ah[mt], bh[2 * t2], bh[2 * t2 + 1]); // Wh*Xh
                        mma_bf16(acc[mt][nidx], ah[mt], bl[2 * t2], bl[2 * t2 + 1]); // Wh*Xl
                        mma_bf16(acc[mt][nidx], al[mt], bh[2 * t2], bh[2 * t2 + 1]); // Wl*Xh
                    }
                }
            }
        }
    }

    // ---- epilogue in 4 slices of 32 channels (Ds32 overlaps tile smem) ----
    float* Ds = reinterpret_cast<float*>(smem);
    float* outb = out + (size_t)b * 64 * OUTG;

    for (int s = 0; s < 4; s++) {
        __syncthreads();   // prior slice reads done / mainloop reads done
        if (wm == s) {     // 2 warps (wn=0,1) own rows [s*32, s*32+32)
            const int r0l = lane >> 2;
            const int cb  = wn * 64 + (lane & 3) * 2;
            #pragma unroll
            for (int mt = 0; mt < 2; mt++) {
                #pragma unroll
                for (int nidx = 0; nidx < 8; nidx++) {
                    const int rr = r0l + mt * 16;
                    const int cc = cb + nidx * 8;
                    Ds[rr * DS_STRIDE + cc]           = acc[mt][nidx][0];
                    Ds[rr * DS_STRIDE + cc + 1]       = acc[mt][nidx][1];
                    Ds[(rr + 8) * DS_STRIDE + cc]     = acc[mt][nidx][2];
                    Ds[(rr + 8) * DS_STRIDE + cc + 1] = acc[mt][nidx][3];
                }
            }
        }
        __syncthreads();

        // Haar: warp wid -> local channels wid*4..+3 (one group), lane -> 4 pixels
        const int chl = wid * 4;
        const int g   = (m0 + s * 32 + chl) >> 2;
        const float b0 = __ldg(bias + m0 + s * 32 + chl + 0);
        const float b1 = __ldg(bias + m0 + s * 32 + chl + 1);
        const float b2 = __ldg(bias + m0 + s * 32 + chl + 2);
        const float b3 = __ldg(bias + m0 + s * 32 + chl + 3);
        const int j0 = lane * 4;
        float4 y0 = *reinterpret_cast<const float4*>(Ds + (chl + 0) * DS_STRIDE + j0);
        float4 y1 = *reinterpret_cast<const float4*>(Ds + (chl + 1) * DS_STRIDE + j0);
        float4 y2 = *reinterpret_cast<const float4*>(Ds + (chl + 2) * DS_STRIDE + j0);
        float4 y3 = *reinterpret_cast<const float4*>(Ds + (chl + 3) * DS_STRIDE + j0);

        float r0v[8], r1v[8];
        {
            const float a0[4] = {y0.x, y0.y, y0.z, y0.w};
            const float a1[4] = {y1.x, y1.y, y1.z, y1.w};
            const float a2[4] = {y2.x, y2.y, y2.z, y2.w};
            const float a3[4] = {y3.x, y3.y, y3.z, y3.w};
            #pragma unroll
            for (int jj = 0; jj < 4; jj++) {
                float v0 = a0[jj] + b0, v1 = a1[jj] + b1;
                float v2 = a2[jj] + b2, v3 = a3[jj] + b3;
                float p = v0 + v1, q = v2 + v3;
                float r = v0 - v1, t = v2 - v3;
                r0v[2 * jj + 0] = 0.5f * (p + q);
                r0v[2 * jj + 1] = 0.5f * (p - q);
                r1v[2 * jj + 0] = 0.5f * (r + t);
                r1v[2 * jj + 1] = 0.5f * (r - t);
            }
        }
        float* o0 = outb + (size_t)g * OUTG + (size_t)(2 * h) * 256 + 2 * j0;
        float* o1 = o0 + 256;
        *reinterpret_cast<float4*>(o0)     = make_float4(r0v[0], r0v[1], r0v[2], r0v[3]);
        *reinterpret_cast<float4*>(o0 + 4) = make_float4(r0v[4], r0v[5], r0v[6], r0v[7]);
        *reinterpret_cast<float4*>(o1)     = make_float4(r1v[0], r1v[1], r1v[2], r1v[3]);
        *reinterpret_cast<float4*>(o1 + 4) = make_float4(r1v[4], r1v[5], r1v[6], r1v[7]);
    }
}

extern "C" void kernel_launch(void* const* d_in, const int* in_sizes, int n_in,
                              void* d_out, int out_size)
{
    const float* x    = (const float*)d_in[0];   // [16,256,128,128]
    const float* w    = (const float*)d_in[1];   // [256,256]
    const float* bias = (const float*)d_in[2];   // [256]
    float* out        = (float*)d_out;           // [16,64,256,256]

    dim3 grid(HH, 2, 16);   // 4096 CTAs
    iwt_hmma_kernel<<<grid, 256>>>(x, w, bias, out);
}

// round 8
// speedup vs baseline: 2.8627x; 1.2886x over previous
#include <cuda_runtime.h>
#include <cuda_fp16.h>
#include <cstdint>

// IWTBlock via mma.sync fp16 2-split GEMM (Wh*X + Wl*X), fp32 acc.
// W split into fp16 hi+lo (22-bit effective); X single fp16 (error ~2^-11 RMS,
// well under the 1e-3 threshold). Double-buffered K chunks overlap conversion
// with HMMA. Static smem only (48KB exactly) -- no dynamic-smem opt-in.
// Per batch: Y = W(256x256) @ X(256x16384) + bias; inverse-Haar epilogue.
// CTA: M=128 oc x N=128 px (one h-row), K=256 in 8 chunks of 32, 2 stages.
// 8 warps: wm=wid&3 (32 oc rows), wn=wid>>2 (64 px cols). Warp tile 32x64.

static constexpr int C_IN = 256;
static constexpr int HH = 128, WW = 128;
static constexpr int PIX = HH * WW;
static constexpr int OUTG = 4 * PIX;
static constexpr int KCH = 32;
static constexpr int NCHUNKS = C_IN / KCH;     // 8

// Per stage: Ah [128m][32k] fp16 (64B rows, 8KB), Al 8KB, Bx [32k][128n] (256B rows, 8KB).
static constexpr int SM_AH = 0;
static constexpr int SM_AL = 8192;
static constexpr int SM_BX = 16384;
static constexpr int STAGE = 24576;
static constexpr int SMEM_BYTES = 2 * STAGE;   // 49152 = 48KB static (max, no opt-in)
static constexpr int DS_STRIDE = 132;          // epilogue floats/row; float4-aligned

__device__ __forceinline__ uint32_t smem_u32(const void* p) {
    uint32_t a;
    asm("{ .reg .u64 t; cvta.to.shared.u64 t, %1; cvt.u32.u64 %0, t; }" : "=r"(a) : "l"(p));
    return a;
}
// A swizzle (64B rows, SW64): XOR bits[4:5] with bits[7:8]
__device__ __forceinline__ uint32_t swA(uint32_t o) { return o ^ ((o >> 3) & 0x30); }
// B swizzle (256B rows): XOR bits[4:6] with bits[8:10]
__device__ __forceinline__ uint32_t swB(uint32_t o) { return o ^ ((o >> 4) & 0x70); }

__device__ __forceinline__ void ldsm_x4(uint32_t (&r)[4], uint32_t addr) {
    asm volatile("ldmatrix.sync.aligned.m8n8.x4.shared.b16 {%0,%1,%2,%3}, [%4];"
                 : "=r"(r[0]), "=r"(r[1]), "=r"(r[2]), "=r"(r[3]) : "r"(addr));
}
__device__ __forceinline__ void ldsm_x4_t(uint32_t (&r)[4], uint32_t addr) {
    asm volatile("ldmatrix.sync.aligned.m8n8.x4.trans.shared.b16 {%0,%1,%2,%3}, [%4];"
                 : "=r"(r[0]), "=r"(r[1]), "=r"(r[2]), "=r"(r[3]) : "r"(addr));
}
__device__ __forceinline__ void mma_f16(float (&d)[4], const uint32_t (&a)[4],
                                        uint32_t b0, uint32_t b1) {
    asm volatile("mma.sync.aligned.m16n8k16.row.col.f32.f16.f16.f32 "
                 "{%0,%1,%2,%3}, {%4,%5,%6,%7}, {%8,%9}, {%0,%1,%2,%3};"
                 : "+f"(d[0]), "+f"(d[1]), "+f"(d[2]), "+f"(d[3])
                 : "r"(a[0]), "r"(a[1]), "r"(a[2]), "r"(a[3]), "r"(b0), "r"(b1));
}

__device__ __forceinline__ uint32_t pk2(float a, float b) {
    __half2 h = __floats2half2_rn(a, b);
    return *reinterpret_cast<uint32_t*>(&h);
}
__device__ __forceinline__ uint32_t pk2_hi(float a, float b, float& ra, float& rb) {
    __half ha = __float2half_rn(a), hb = __float2half_rn(b);
    ra = a - __half2float(ha);
    rb = b - __half2float(hb);
    __half2 h = __halves2half2(ha, hb);
    return *reinterpret_cast<uint32_t*>(&h);
}

__global__ __launch_bounds__(256, 2)
void iwt_hmma2_kernel(const float* __restrict__ x,
                      const float* __restrict__ wmat,
                      const float* __restrict__ bias,
                      float* __restrict__ out)
{
    __shared__ __align__(1024) char smem[SMEM_BYTES];
    const uint32_t sb = smem_u32(smem);
    const int tid = threadIdx.x, wid = tid >> 5, lane = tid & 31;
    const int b = blockIdx.z, m0 = blockIdx.y * 128, h = blockIdx.x;
    const float* Xb = x + ((size_t)b * C_IN) * PIX + (size_t)h * WW;

    const int wm = wid & 3;          // m-block
    const int wn = wid >> 2;         // n-block

    // W conversion: tid&7 -> k4, tid>>3 -> row (+32*it)
    const int wk4   = (tid & 7) * 4;
    const int wrow0 = tid >> 3;
    // X conversion: tid&15 -> n8, tid>>4 -> k (+16*it)
    const int xn8 = (tid & 15) * 8;
    const int xk0 = tid >> 4;

    // ldmatrix lane addressing
    const int li  = lane & 7;
    const int seg = lane >> 3;
    const int a_row_off = li + (seg & 1) * 8;
    const int a_col_off = (seg >> 1) * 8;
    const int b_k_off = li + (seg & 1) * 8;
    const int b_n_off = (seg >> 1) * 8;

    float acc[2][8][4];
    #pragma unroll
    for (int i = 0; i < 2; i++)
        #pragma unroll
        for (int j = 0; j < 8; j++)
            #pragma unroll
            for (int v = 0; v < 4; v++) acc[i][j][v] = 0.f;

    // ---- prologue: convert chunk 0 into stage 0 ----
    {
        #pragma unroll
        for (int it = 0; it < 4; it++) {
            const int row = wrow0 + 32 * it;
            float4 v = *reinterpret_cast<const float4*>(
                wmat + (size_t)(m0 + row) * C_IN + wk4);
            float r0, r1, r2, r3;
            uint32_t h01 = pk2_hi(v.x, v.y, r0, r1);
            uint32_t h23 = pk2_hi(v.z, v.w, r2, r3);
            uint32_t off = swA((uint32_t)(row * 64 + wk4 * 2));
            *reinterpret_cast<uint2*>(smem + SM_AH + off) = make_uint2(h01, h23);
            *reinterpret_cast<uint2*>(smem + SM_AL + off) = make_uint2(pk2(r0, r1), pk2(r2, r3));
        }
        #pragma unroll
        for (int it = 0; it < 2; it++) {
            const int k = xk0 + 16 * it;
            const float* src = Xb + (size_t)k * PIX + xn8;
            float4 v0 = *reinterpret_cast<const float4*>(src);
            float4 v1 = *reinterpret_cast<const float4*>(src + 4);
            uint32_t off = swB((uint32_t)(k * 256 + xn8 * 2));
            *reinterpret_cast<uint4*>(smem + SM_BX + off) =
                make_uint4(pk2(v0.x, v0.y), pk2(v0.z, v0.w),
                           pk2(v1.x, v1.y), pk2(v1.z, v1.w));
        }
    }
    __syncthreads();

    for (int c = 0; c < NCHUNKS; c++) {
        // ---- prefetch X for chunk c+1 (LDGs fly during MMA block) ----
        float4 xv[4];
        if (c < NCHUNKS - 1) {
            const int kb1 = (c + 1) * KCH;
            #pragma unroll
            for (int it = 0; it < 2; it++) {
                const float* src = Xb + (size_t)(kb1 + xk0 + 16 * it) * PIX + xn8;
                xv[2 * it]     = *reinterpret_cast<const float4*>(src);
                xv[2 * it + 1] = *reinterpret_cast<const float4*>(src + 4);
            }
        }

        // ---- MMA on stage c&1: 2 k16 steps, 32 HMMA each ----
        const uint32_t base = sb + (uint32_t)(c & 1) * STAGE;
        #pragma unroll
        for (int s = 0; s < 2; s++) {
            const int k0 = s * 16;
            uint32_t ah[2][4], al[2][4];
            #pragma unroll
            for (int mt = 0; mt < 2; mt++) {
                const int R = wm * 32 + mt * 16 + a_row_off;
                const uint32_t aoff = swA((uint32_t)(R * 64 + (k0 + a_col_off) * 2));
                ldsm_x4(ah[mt], base + SM_AH + aoff);
                ldsm_x4(al[mt], base + SM_AL + aoff);
            }
            #pragma unroll
            for (int nt = 0; nt < 4; nt++) {
                const int n0 = wn * 64 + nt * 16;
                const uint32_t boff = swB((uint32_t)((k0 + b_k_off) * 256 +
                                                     (n0 + b_n_off) * 2));
                uint32_t bx[4];
                ldsm_x4_t(bx, base + SM_BX + boff);
                #pragma unroll
                for (int t2 = 0; t2 < 2; t2++) {
                    const int nidx = nt * 2 + t2;
                    #pragma unroll
                    for (int mt = 0; mt < 2; mt++) {
                        mma_f16(acc[mt][nidx], ah[mt], bx[2 * t2], bx[2 * t2 + 1]); // Wh*X
                        mma_f16(acc[mt][nidx], al[mt], bx[2 * t2], bx[2 * t2 + 1]); // Wl*X
                    }
                }
            }
        }

        // ---- convert chunk c+1 into stage (c+1)&1 ----
        if (c < NCHUNKS - 1) {
            const int kb1 = (c + 1) * KCH;
            char* nb = smem + ((c + 1) & 1) * STAGE;
            #pragma unroll
            for (int it = 0; it < 4; it++) {           // W: LDG (L2-hot) + split
                const int row = wrow0 + 32 * it;
                float4 v = *reinterpret_cast<const float4*>(
                    wmat + (size_t)(m0 + row) * C_IN + kb1 + wk4);
                float r0, r1, r2, r3;
                uint32_t h01 = pk2_hi(v.x, v.y, r0, r1);
                uint32_t h23 = pk2_hi(v.z, v.w, r2, r3);
                uint32_t off = swA((uint32_t)(row * 64 + wk4 * 2));
                *reinterpret_cast<uint2*>(nb + SM_AH + off) = make_uint2(h01, h23);
                *reinterpret_cast<uint2*>(nb + SM_AL + off) = make_uint2(pk2(r0, r1), pk2(r2, r3));
            }
            #pragma unroll
            for (int it = 0; it < 2; it++) {           // X: cvt from prefetched regs
                const int k = xk0 + 16 * it;
                const float4 v0 = xv[2 * it], v1 = xv[2 * it + 1];
                uint32_t off = swB((uint32_t)(k * 256 + xn8 * 2));
                *reinterpret_cast<uint4*>(nb + SM_BX + off) =
                    make_uint4(pk2(v0.x, v0.y), pk2(v0.z, v0.w),
                               pk2(v1.x, v1.y), pk2(v1.z, v1.w));
            }
        }
        __syncthreads();
    }

    // ---- epilogue in 4 slices of 32 channels (Ds overlaps tile smem) ----
    float* Ds = reinterpret_cast<float*>(smem);
    float* outb = out + (size_t)b * 64 * OUTG;

    for (int s = 0; s < 4; s++) {
        if (s > 0) __syncthreads();
        if (wm == s) {     // 2 warps (wn=0,1) own rows [s*32, s*32+32)
            const int r0l = lane >> 2;
            const int cb  = wn * 64 + (lane & 3) * 2;
            #pragma unroll
            for (int mt = 0; mt < 2; mt++) {
                #pragma unroll
                for (int nidx = 0; nidx < 8; nidx++) {
                    const int rr = r0l + mt * 16;
                    const int cc = cb + nidx * 8;
                    Ds[rr * DS_STRIDE + cc]           = acc[mt][nidx][0];
                    Ds[rr * DS_STRIDE + cc + 1]       = acc[mt][nidx][1];
                    Ds[(rr + 8) * DS_STRIDE + cc]     = acc[mt][nidx][2];
                    Ds[(rr + 8) * DS_STRIDE + cc + 1] = acc[mt][nidx][3];
                }
            }
        }
        __syncthreads();

        // Haar: warp wid -> local channels wid*4..+3 (one group), lane -> 4 pixels
        const int chl = wid * 4;
        const int g   = (m0 + s * 32 + chl) >> 2;
        const float b0 = __ldg(bias + m0 + s * 32 + chl + 0);
        const float b1 = __ldg(bias + m0 + s * 32 + chl + 1);
        const float b2 = __ldg(bias + m0 + s * 32 + chl + 2);
        const float b3 = __ldg(bias + m0 + s * 32 + chl + 3);
        const int j0 = lane * 4;
        float4 y0 = *reinterpret_cast<const float4*>(Ds + (chl + 0) * DS_STRIDE + j0);
        float4 y1 = *reinterpret_cast<const float4*>(Ds + (chl + 1) * DS_STRIDE + j0);
        float4 y2 = *reinterpret_cast<const float4*>(Ds + (chl + 2) * DS_STRIDE + j0);
        float4 y3 = *reinterpret_cast<const float4*>(Ds + (chl + 3) * DS_STRIDE + j0);

        float r0v[8], r1v[8];
        {
            const float a0[4] = {y0.x, y0.y, y0.z, y0.w};
            const float a1[4] = {y1.x, y1.y, y1.z, y1.w};
            const float a2[4] = {y2.x, y2.y, y2.z, y2.w};
            const float a3[4] = {y3.x, y3.y, y3.z, y3.w};
            #pragma unroll
            for (int jj = 0; jj < 4; jj++) {
                float v0 = a0[jj] + b0, v1 = a1[jj] + b1;
                float v2 = a2[jj] + b2, v3 = a3[jj] + b3;
                float p = v0 + v1, q = v2 + v3;
                float r = v0 - v1, t = v2 - v3;
                r0v[2 * jj + 0] = 0.5f * (p + q);
                r0v[2 * jj + 1] = 0.5f * (p - q);
                r1v[2 * jj + 0] = 0.5f * (r + t);
                r1v[2 * jj + 1] = 0.5f * (r - t);
            }
        }
        float* o0 = outb + (size_t)g * OUTG + (size_t)(2 * h) * 256 + 2 * j0;
        float* o1 = o0 + 256;
        *reinterpret_cast<float4*>(o0)     = make_float4(r0v[0], r0v[1], r0v[2], r0v[3]);
        *reinterpret_cast<float4*>(o0 + 4) = make_float4(r0v[4], r0v[5], r0v[6], r0v[7]);
        *reinterpret_cast<float4*>(o1)     = make_float4(r1v[0], r1v[1], r1v[2], r1v[3]);
        *reinterpret_cast<float4*>(o1 + 4) = make_float4(r1v[4], r1v[5], r1v[6], r1v[7]);
    }
}

extern "C" void kernel_launch(void* const* d_in, const int* in_sizes, int n_in,
                              void* d_out, int out_size)
{
    const float* x    = (const float*)d_in[0];   // [16,256,128,128]
    const float* w    = (const float*)d_in[1];   // [256,256]
    const float* bias = (const float*)d_in[2];   // [256]
    float* out        = (float*)d_out;           // [16,64,256,256]

    dim3 grid(HH, 2, 16);   // 4096 CTAs
    iwt_hmma2_kernel<<<grid, 256>>>(x, w, bias, out);
}